// round 7
// baseline (speedup 1.0000x reference)
#include <cuda_runtime.h>
#include <math.h>
#include <stdint.h>

// Problem constants
#define Nn   256
#define Ll   384
#define Dd   256
#define DP   128
#define Hh   8
#define DHh  32
#define NL   (Nn*Ll)      // 98304 rows
#define LLp  (Ll*Ll)      // 147456
#define EPSF 1e-5f
#define SCALE 0.17677669529663687f  // 1/sqrt(32)

// ---------------- scratch (device globals; no allocation allowed) ----------------
__device__ float g_q   [NL*Dd];   // q projection (raw; seq-weight applied at load)
__device__ float g_k   [NL*Dd];   // k projection (scaled)
__device__ float g_v   [NL*Dd];   // v projection
__device__ float g_g   [NL*Dd];   // gate
__device__ float g_o   [NL*Dd];   // attention output (gated)
__device__ float g_qsw [Ll*Dd];   // seq-weight queries
__device__ float g_sw  [NL*Hh];   // sw logits -> seq weights
__device__ float g_logits[Hh*LLp]; // logits(+bias) -> attn
__device__ float g_bias  [Hh*LLp]; // pair bias
__device__ float g_mu  [NL];
__device__ float g_rs  [NL];

// ---------------- tf32 helpers ----------------
__device__ __forceinline__ uint32_t f2tf32(float f) {
    uint32_t r;
    asm("cvt.rna.tf32.f32 %0, %1;" : "=r"(r) : "f"(f));
    return r;
}

__device__ __forceinline__ void mma_tf32(float& c0, float& c1, float& c2, float& c3,
                                         uint32_t a0, uint32_t a1, uint32_t a2, uint32_t a3,
                                         uint32_t b0, uint32_t b1) {
    asm volatile("mma.sync.aligned.m16n8k8.row.col.f32.tf32.tf32.f32 "
                 "{%0,%1,%2,%3}, {%4,%5,%6,%7}, {%8,%9}, {%0,%1,%2,%3};"
                 : "+f"(c0), "+f"(c1), "+f"(c2), "+f"(c3)
                 : "r"(a0), "r"(a1), "r"(a2), "r"(a3), "r"(b0), "r"(b1));
}

// ---------------- per-row mean/rstd of msa (warp per row) ----------------
__global__ void rowstat_kernel(const float* __restrict__ x,
                               float* __restrict__ mu, float* __restrict__ rs) {
    int row = blockIdx.x * 8 + (threadIdx.x >> 5);
    int lane = threadIdx.x & 31;
    const float4* xp = (const float4*)(x + (size_t)row*Dd);
    float s = 0.f, q = 0.f;
    #pragma unroll
    for (int u = 0; u < 2; u++) {
        float4 v = xp[lane + u*32];
        s += v.x + v.y + v.z + v.w;
        q += v.x*v.x + v.y*v.y + v.z*v.z + v.w*v.w;
    }
    #pragma unroll
    for (int o = 16; o; o >>= 1) {
        s += __shfl_xor_sync(0xffffffffu, s, o);
        q += __shfl_xor_sync(0xffffffffu, q, o);
    }
    if (!lane) {
        float m = s * (1.0f/Dd);
        mu[row] = m;
        rs[row] = rsqrtf(q * (1.0f/Dd) - m*m + EPSF);
    }
}

// ============================================================================
// TF32 GEMM: C[Mx256] = (optLN(A) @ W + bias)*scale ; optional sigmoid.
// BM=128, BN=128, BK=32, 256 threads (8 warps 4x2), warp tile 32x64.
// ============================================================================
template<bool LN, bool SIG, bool BIAS>
__global__ void __launch_bounds__(256) gemm256_tf32(
        const float* __restrict__ A, const float* __restrict__ W,
        const float* __restrict__ bias,
        const float* __restrict__ mu, const float* __restrict__ rs,
        const float* __restrict__ lng, const float* __restrict__ lnb,
        float scale, float* __restrict__ C) {
    __shared__ uint32_t As[128][36];
    __shared__ uint32_t Bs[32][136];
    int tid = threadIdx.x;
    int wid = tid >> 5, lane = tid & 31;
    int gid = lane >> 2, tig = lane & 3;
    int wm0 = (wid >> 1) * 32;
    int wn0 = (wid & 1) * 64;
    int m0 = blockIdx.y * 128, n0 = blockIdx.x * 128;

    float acc[2][8][4] = {};

    for (int kt = 0; kt < 8; kt++) {
        int k0 = kt * 32;
        #pragma unroll
        for (int u = 0; u < 4; u++) {
            int f = tid + u*256;
            int row = f >> 3, c4 = f & 7;
            float4 v = *(const float4*)(A + (size_t)(m0+row)*Dd + k0 + c4*4);
            if (LN) {
                float muv = mu[m0+row], rsv = rs[m0+row];
                float4 g4 = *(const float4*)(lng + k0 + c4*4);
                float4 b4 = *(const float4*)(lnb + k0 + c4*4);
                v.x = (v.x - muv)*rsv*g4.x + b4.x;
                v.y = (v.y - muv)*rsv*g4.y + b4.y;
                v.z = (v.z - muv)*rsv*g4.z + b4.z;
                v.w = (v.w - muv)*rsv*g4.w + b4.w;
            }
            uint4 tv;
            tv.x = f2tf32(v.x); tv.y = f2tf32(v.y);
            tv.z = f2tf32(v.z); tv.w = f2tf32(v.w);
            *(uint4*)&As[row][c4*4] = tv;
        }
        #pragma unroll
        for (int u = 0; u < 4; u++) {
            int f = tid + u*256;
            int kr = f >> 5, c4 = f & 31;
            float4 v = *(const float4*)(W + (size_t)(k0+kr)*Dd + n0 + c4*4);
            uint4 tv;
            tv.x = f2tf32(v.x); tv.y = f2tf32(v.y);
            tv.z = f2tf32(v.z); tv.w = f2tf32(v.w);
            *(uint4*)&Bs[kr][c4*4] = tv;
        }
        __syncthreads();
        #pragma unroll
        for (int kk = 0; kk < 4; kk++) {
            int kb = kk * 8;
            uint32_t a[2][4];
            #pragma unroll
            for (int mf = 0; mf < 2; mf++) {
                int r = wm0 + mf*16 + gid;
                a[mf][0] = As[r][kb + tig];
                a[mf][1] = As[r+8][kb + tig];
                a[mf][2] = As[r][kb + tig + 4];
                a[mf][3] = As[r+8][kb + tig + 4];
            }
            uint32_t b[8][2];
            #pragma unroll
            for (int nf = 0; nf < 8; nf++) {
                int cn = wn0 + nf*8 + gid;
                b[nf][0] = Bs[kb + tig][cn];
                b[nf][1] = Bs[kb + tig + 4][cn];
            }
            #pragma unroll
            for (int mf = 0; mf < 2; mf++)
                #pragma unroll
                for (int nf = 0; nf < 8; nf++)
                    mma_tf32(acc[mf][nf][0], acc[mf][nf][1], acc[mf][nf][2], acc[mf][nf][3],
                             a[mf][0], a[mf][1], a[mf][2], a[mf][3],
                             b[nf][0], b[nf][1]);
        }
        __syncthreads();
    }
    #pragma unroll
    for (int mf = 0; mf < 2; mf++) {
        #pragma unroll
        for (int half = 0; half < 2; half++) {
            int row = m0 + wm0 + mf*16 + gid + half*8;
            #pragma unroll
            for (int nf = 0; nf < 8; nf++) {
                int col = n0 + wn0 + nf*8 + tig*2;
                float v0 = acc[mf][nf][half*2 + 0];
                float v1 = acc[mf][nf][half*2 + 1];
                if (BIAS) { v0 += bias[col]; v1 += bias[col+1]; }
                v0 *= scale; v1 *= scale;
                if (SIG) {
                    v0 = 1.f / (1.f + expf(-v0));
                    v1 = 1.f / (1.f + expf(-v1));
                }
                float2 o; o.x = v0; o.y = v1;
                *(float2*)(C + (size_t)row*Dd + col) = o;
            }
        }
    }
}

// ============================================================================
// Fused projection kernel: one pass over msa (LN on the fly), 5 weight matrices.
// BM=128, BN=256 (full width), K=256 resident in smem. 512 threads (16 warps 4x4).
//   mat 0: Wk_sw -> sw_logits (epilogue dot with qsw, no store of ksw)
//   mat 1: Wq -> qo
//   mat 2: Wk -> ko (* SCALE)
//   mat 3: Wv -> vo
//   mat 4: Wg -> go (sigmoid(x + bg))
// ============================================================================
#define FP_AF_STRIDE 260
#define FP_WS_STRIDE 264
#define FP_SMEM_BYTES ((128*FP_AF_STRIDE + 32*FP_WS_STRIDE) * 4)

__global__ void __launch_bounds__(512) fusedproj_kernel(
        const float* __restrict__ msa,
        const float* __restrict__ mu, const float* __restrict__ rs,
        const float* __restrict__ lng, const float* __restrict__ lnb,
        const float* __restrict__ Wksw, const float* __restrict__ bksw,
        const float* __restrict__ Wq, const float* __restrict__ Wk,
        const float* __restrict__ Wv, const float* __restrict__ Wg,
        const float* __restrict__ bg, const float* __restrict__ qsw,
        float* __restrict__ qo, float* __restrict__ ko,
        float* __restrict__ vo, float* __restrict__ go,
        float* __restrict__ swl) {
    extern __shared__ uint32_t sh[];
    uint32_t (*Af)[FP_AF_STRIDE] = (uint32_t(*)[FP_AF_STRIDE])sh;
    uint32_t (*Ws)[FP_WS_STRIDE] = (uint32_t(*)[FP_WS_STRIDE])(sh + 128*FP_AF_STRIDE);
    int tid = threadIdx.x;
    int wid = tid >> 5, lane = tid & 31;
    int gid = lane >> 2, tig = lane & 3;
    int wm0 = (wid >> 2) * 32;     // 4 m-groups
    int wn0 = (wid & 3) * 64;      // 4 n-groups
    int m0 = blockIdx.x * 128;

    // Load full A block 128x256 with LN applied, converted to tf32.
    #pragma unroll
    for (int u = 0; u < 16; u++) {
        int f = tid + u*512;          // 0..8191 float4 slots
        int row = f >> 6, c4 = f & 63;
        float4 v = *(const float4*)(msa + (size_t)(m0+row)*Dd + c4*4);
        float muv = mu[m0+row], rsv = rs[m0+row];
        float4 g4 = *(const float4*)(lng + c4*4);
        float4 b4 = *(const float4*)(lnb + c4*4);
        uint4 t;
        t.x = f2tf32((v.x - muv)*rsv*g4.x + b4.x);
        t.y = f2tf32((v.y - muv)*rsv*g4.y + b4.y);
        t.z = f2tf32((v.z - muv)*rsv*g4.z + b4.z);
        t.w = f2tf32((v.w - muv)*rsv*g4.w + b4.w);
        *(uint4*)&Af[row][c4*4] = t;
    }

    const float* Wlist[5] = {Wksw, Wq, Wk, Wv, Wg};

    for (int mat = 0; mat < 5; mat++) {
        const float* W = Wlist[mat];
        float acc[2][8][4] = {};
        for (int kt = 0; kt < 8; kt++) {
            __syncthreads();   // protect Ws (and Af on first iter)
            #pragma unroll
            for (int u = 0; u < 4; u++) {
                int f = tid + u*512;       // 0..2047 float4 slots (32x64)
                int row = f >> 6, c4 = f & 63;
                float4 v = *(const float4*)(W + (size_t)(kt*32+row)*Dd + c4*4);
                uint4 t;
                t.x = f2tf32(v.x); t.y = f2tf32(v.y);
                t.z = f2tf32(v.z); t.w = f2tf32(v.w);
                *(uint4*)&Ws[row][c4*4] = t;
            }
            __syncthreads();
            #pragma unroll
            for (int kk = 0; kk < 4; kk++) {
                int ka = kt*32 + kk*8;     // Af column base
                int kb = kk*8;             // Ws row base
                uint32_t a[2][4];
                #pragma unroll
                for (int mf = 0; mf < 2; mf++) {
                    int r = wm0 + mf*16 + gid;
                    a[mf][0] = Af[r][ka + tig];
                    a[mf][1] = Af[r+8][ka + tig];
                    a[mf][2] = Af[r][ka + tig + 4];
                    a[mf][3] = Af[r+8][ka + tig + 4];
                }
                uint32_t b[8][2];
                #pragma unroll
                for (int nf = 0; nf < 8; nf++) {
                    int cn = wn0 + nf*8 + gid;
                    b[nf][0] = Ws[kb + tig][cn];
                    b[nf][1] = Ws[kb + tig + 4][cn];
                }
                #pragma unroll
                for (int mf = 0; mf < 2; mf++)
                    #pragma unroll
                    for (int nf = 0; nf < 8; nf++)
                        mma_tf32(acc[mf][nf][0], acc[mf][nf][1], acc[mf][nf][2], acc[mf][nf][3],
                                 a[mf][0], a[mf][1], a[mf][2], a[mf][3],
                                 b[nf][0], b[nf][1]);
            }
        }
        // epilogue
        if (mat == 0) {
            // sw_logits[row][head] = sum_d (ksw[row,d]) * qsw[i,d], i = row % L
            #pragma unroll
            for (int mf = 0; mf < 2; mf++) {
                #pragma unroll
                for (int half = 0; half < 2; half++) {
                    int row = m0 + wm0 + mf*16 + gid + half*8;
                    int i = row % Ll;
                    float p0 = 0.f, p1 = 0.f;
                    #pragma unroll
                    for (int nf = 0; nf < 8; nf++) {
                        int col = wn0 + nf*8 + tig*2;
                        float v0 = acc[mf][nf][half*2 + 0] + bksw[col];
                        float v1 = acc[mf][nf][half*2 + 1] + bksw[col+1];
                        float2 qv = *(const float2*)(qsw + (size_t)i*Dd + col);
                        float contrib = v0*qv.x + v1*qv.y;
                        if (nf < 4) p0 += contrib; else p1 += contrib;
                    }
                    p0 += __shfl_xor_sync(0xffffffffu, p0, 1);
                    p0 += __shfl_xor_sync(0xffffffffu, p0, 2);
                    p1 += __shfl_xor_sync(0xffffffffu, p1, 1);
                    p1 += __shfl_xor_sync(0xffffffffu, p1, 2);
                    if (tig == 0) {
                        int hbase = wn0 >> 5;
                        swl[(size_t)row*Hh + hbase]     = p0;
                        swl[(size_t)row*Hh + hbase + 1] = p1;
                    }
                }
            }
        } else {
            float* C = (mat == 1) ? qo : (mat == 2) ? ko : (mat == 3) ? vo : go;
            float scl = (mat == 2) ? SCALE : 1.f;
            bool sig = (mat == 4);
            #pragma unroll
            for (int mf = 0; mf < 2; mf++) {
                #pragma unroll
                for (int half = 0; half < 2; half++) {
                    int row = m0 + wm0 + mf*16 + gid + half*8;
                    #pragma unroll
                    for (int nf = 0; nf < 8; nf++) {
                        int col = wn0 + nf*8 + tig*2;
                        float v0 = acc[mf][nf][half*2 + 0];
                        float v1 = acc[mf][nf][half*2 + 1];
                        if (mat == 4) { v0 += bg[col]; v1 += bg[col+1]; }
                        v0 *= scl; v1 *= scl;
                        if (sig) {
                            v0 = 1.f / (1.f + expf(-v0));
                            v1 = 1.f / (1.f + expf(-v1));
                        }
                        float2 o; o.x = v0; o.y = v1;
                        *(float2*)(C + (size_t)row*Dd + col) = o;
                    }
                }
            }
        }
    }
}

// ---------------- softmax over n (256) for each (i,h) ----------------
__global__ void swsoftmax_kernel(float* __restrict__ sw) {
    __shared__ float sm[8];
    __shared__ float red;
    int ih = blockIdx.x;             // i*H + h
    int n = threadIdx.x;             // 256
    int lane = n & 31, w = n >> 5;
    float v = sw[(size_t)n*(Ll*Hh) + ih];
    float mx = v;
    #pragma unroll
    for (int o = 16; o; o >>= 1) mx = fmaxf(mx, __shfl_down_sync(0xffffffffu, mx, o));
    if (!lane) sm[w] = mx;
    __syncthreads();
    if (w == 0) {
        float x = (lane < 8) ? sm[lane] : -3.4e38f;
        #pragma unroll
        for (int o = 16; o; o >>= 1) x = fmaxf(x, __shfl_down_sync(0xffffffffu, x, o));
        if (!lane) red = x;
    }
    __syncthreads();
    mx = red;
    float e = expf(v - mx);
    float s = e;
    #pragma unroll
    for (int o = 16; o; o >>= 1) s += __shfl_down_sync(0xffffffffu, s, o);
    __syncthreads();
    if (!lane) sm[w] = s;
    __syncthreads();
    if (w == 0) {
        float x = (lane < 8) ? sm[lane] : 0.f;
        #pragma unroll
        for (int o = 16; o; o >>= 1) x += __shfl_down_sync(0xffffffffu, x, o);
        if (!lane) red = x;
    }
    __syncthreads();
    sw[(size_t)n*(Ll*Hh) + ih] = e / red;
}

// ---------------- pair bias: LN(pair row) @ Wb -> bias[h][i][j] ----------------
__global__ void pairbias_kernel(const float* __restrict__ pair, const float* __restrict__ g,
                                const float* __restrict__ b, const float* __restrict__ Wb,
                                float* __restrict__ bias) {
    __shared__ float s1[4], s2[4];
    __shared__ float hp[4][8];
    int ij = blockIdx.x;             // i*L + j
    int t = threadIdx.x;             // 128
    int lane = t & 31, w = t >> 5;
    float v = pair[(size_t)ij*DP + t];
    float s = v, q = v*v;
    #pragma unroll
    for (int o = 16; o; o >>= 1) {
        s += __shfl_down_sync(0xffffffffu, s, o);
        q += __shfl_down_sync(0xffffffffu, q, o);
    }
    if (!lane) { s1[w] = s; s2[w] = q; }
    __syncthreads();
    if (w == 0) {
        float ss = (lane < 4) ? s1[lane] : 0.f;
        float qq = (lane < 4) ? s2[lane] : 0.f;
        #pragma unroll
        for (int o = 16; o; o >>= 1) {
            ss += __shfl_down_sync(0xffffffffu, ss, o);
            qq += __shfl_down_sync(0xffffffffu, qq, o);
        }
        if (!lane) { s1[0] = ss; s2[0] = qq; }
    }
    __syncthreads();
    float mu = s1[0] * (1.0f/DP);
    float var = s2[0] * (1.0f/DP) - mu*mu;
    float ln = (v - mu) * rsqrtf(var + EPSF) * g[t] + b[t];
    float p[8];
    #pragma unroll
    for (int h = 0; h < 8; h++) p[h] = ln * Wb[t*Hh + h];
    #pragma unroll
    for (int h = 0; h < 8; h++)
        #pragma unroll
        for (int o = 16; o; o >>= 1) p[h] += __shfl_down_sync(0xffffffffu, p[h], o);
    if (!lane) {
        #pragma unroll
        for (int h = 0; h < 8; h++) hp[w][h] = p[h];
    }
    __syncthreads();
    if (t < 8) {
        float x = hp[0][t] + hp[1][t] + hp[2][t] + hp[3][t];
        bias[(size_t)t*LLp + ij] = x;
    }
}

// ============================================================================
// TF32 logits 128x128: logits[h][i][j] = sum_{n,d} (q*sw)[n,i,h,d]*k[n,j,h,d] + bias
// grid (3, 3, 8), 256 threads (8 warps 4x2).
// ============================================================================
__global__ void __launch_bounds__(256) logits128_tf32(const float* __restrict__ q,
        const float* __restrict__ kmat, const float* __restrict__ sw,
        const float* __restrict__ bias, float* __restrict__ out) {
    __shared__ uint32_t As[128][36];   // q tile [i][d]
    __shared__ uint32_t Bs[128][36];   // k tile [j][d]  (natural, B is n-major)
    int h = blockIdx.z;
    int i0 = blockIdx.y * 128, j0 = blockIdx.x * 128;
    int tid = threadIdx.x;
    int wid = tid >> 5, lane = tid & 31;
    int gid = lane >> 2, tig = lane & 3;
    int wm0 = (wid >> 1) * 32;
    int wn0 = (wid & 1) * 64;

    float acc[2][8][4] = {};

    for (int n = 0; n < Nn; n++) {
        #pragma unroll
        for (int u = 0; u < 4; u++) {
            int f = tid + u*256;
            int row = f >> 3, c4 = f & 7;
            int gi = n*Ll + i0 + row;
            float swv = sw[(size_t)gi*Hh + h];
            float4 a = *(const float4*)(q + (size_t)gi*Dd + h*DHh + c4*4);
            uint4 ta;
            ta.x = f2tf32(a.x*swv); ta.y = f2tf32(a.y*swv);
            ta.z = f2tf32(a.z*swv); ta.w = f2tf32(a.w*swv);
            *(uint4*)&As[row][c4*4] = ta;
            int gj = n*Ll + j0 + row;
            float4 bv = *(const float4*)(kmat + (size_t)gj*Dd + h*DHh + c4*4);
            uint4 tb;
            tb.x = f2tf32(bv.x); tb.y = f2tf32(bv.y);
            tb.z = f2tf32(bv.z); tb.w = f2tf32(bv.w);
            *(uint4*)&Bs[row][c4*4] = tb;
        }
        __syncthreads();
        #pragma unroll
        for (int kk = 0; kk < 4; kk++) {
            int kb = kk * 8;
            uint32_t a[2][4];
            #pragma unroll
            for (int mf = 0; mf < 2; mf++) {
                int r = wm0 + mf*16 + gid;
                a[mf][0] = As[r][kb + tig];
                a[mf][1] = As[r+8][kb + tig];
                a[mf][2] = As[r][kb + tig + 4];
                a[mf][3] = As[r+8][kb + tig + 4];
            }
            uint32_t b[8][2];
            #pragma unroll
            for (int nf = 0; nf < 8; nf++) {
                int cn = wn0 + nf*8 + gid;
                b[nf][0] = Bs[cn][kb + tig];
                b[nf][1] = Bs[cn][kb + tig + 4];
            }
            #pragma unroll
            for (int mf = 0; mf < 2; mf++)
                #pragma unroll
                for (int nf = 0; nf < 8; nf++)
                    mma_tf32(acc[mf][nf][0], acc[mf][nf][1], acc[mf][nf][2], acc[mf][nf][3],
                             a[mf][0], a[mf][1], a[mf][2], a[mf][3],
                             b[nf][0], b[nf][1]);
        }
        __syncthreads();
    }
    #pragma unroll
    for (int mf = 0; mf < 2; mf++) {
        #pragma unroll
        for (int half = 0; half < 2; half++) {
            int i = i0 + wm0 + mf*16 + gid + half*8;
            #pragma unroll
            for (int nf = 0; nf < 8; nf++) {
                int j = j0 + wn0 + nf*8 + tig*2;
                size_t idx = (size_t)h*LLp + (size_t)i*Ll + j;
                float2 bb = *(const float2*)(bias + idx);
                float2 o;
                o.x = acc[mf][nf][half*2 + 0] + bb.x;
                o.y = acc[mf][nf][half*2 + 1] + bb.y;
                *(float2*)(out + idx) = o;
            }
        }
    }
}

// ---------------- softmax over j (384) for each (h, i) ----------------
__global__ void attnsoftmax_kernel(float* __restrict__ logits) {
    __shared__ float sm[12];
    __shared__ float red;
    int hi = blockIdx.x;             // h*L + i
    size_t base = (size_t)hi * Ll;
    int j = threadIdx.x;             // 384 threads, 12 warps
    int lane = j & 31, w = j >> 5;
    float v = logits[base + j];
    float mx = v;
    #pragma unroll
    for (int o = 16; o; o >>= 1) mx = fmaxf(mx, __shfl_down_sync(0xffffffffu, mx, o));
    if (!lane) sm[w] = mx;
    __syncthreads();
    if (w == 0) {
        float x = (lane < 12) ? sm[lane] : -3.4e38f;
        #pragma unroll
        for (int o = 16; o; o >>= 1) x = fmaxf(x, __shfl_down_sync(0xffffffffu, x, o));
        if (!lane) red = x;
    }
    __syncthreads();
    mx = red;
    float e = expf(v - mx);
    float s = e;
    #pragma unroll
    for (int o = 16; o; o >>= 1) s += __shfl_down_sync(0xffffffffu, s, o);
    __syncthreads();
    if (!lane) sm[w] = s;
    __syncthreads();
    if (w == 0) {
        float x = (lane < 12) ? sm[lane] : 0.f;
        #pragma unroll
        for (int o = 16; o; o >>= 1) x += __shfl_down_sync(0xffffffffu, x, o);
        if (!lane) red = x;
    }
    __syncthreads();
    logits[base + j] = e / red;
}

// ============================================================================
// TF32 attn@V 128x128 with fused gate: out = (attn @ v) * gate
// grid (64, 3, 8), 256 threads (8 warps 4x2). c = n_local*32 + d.
// ============================================================================
__global__ void __launch_bounds__(256) outgemm128_tf32(const float* __restrict__ attn,
        const float* __restrict__ v, const float* __restrict__ gate,
        float* __restrict__ out) {
    __shared__ uint32_t As[128][36];   // attn [i][j]
    __shared__ uint32_t Bs[32][136];   // v [j][c]
    int h = blockIdx.z;
    int i0 = blockIdx.y * 128, c0 = blockIdx.x * 128;
    int tid = threadIdx.x;
    int wid = tid >> 5, lane = tid & 31;
    int gid = lane >> 2, tig = lane & 3;
    int wm0 = (wid >> 1) * 32;
    int wn0 = (wid & 1) * 64;

    float acc[2][8][4] = {};

    for (int jt = 0; jt < 12; jt++) {
        int j0 = jt * 32;
        #pragma unroll
        for (int u = 0; u < 4; u++) {
            int f = tid + u*256;
            {   // attn tile 128 i x 32 j
                int row = f >> 3, c4 = f & 7;
                float4 a = *(const float4*)(attn + (size_t)h*LLp + (size_t)(i0 + row)*Ll + j0 + c4*4);
                uint4 ta;
                ta.x = f2tf32(a.x); ta.y = f2tf32(a.y);
                ta.z = f2tf32(a.z); ta.w = f2tf32(a.w);
                *(uint4*)&As[row][c4*4] = ta;
            }
            {   // v tile 32 j x 128 c
                int jrow = f >> 5, cc = f & 31;
                int cg = c0 + cc*4;
                int nn = cg >> 5, dd = cg & 31;
                float4 bv = *(const float4*)(v + (size_t)(nn*Ll + j0 + jrow)*Dd + h*DHh + dd);
                uint4 tb;
                tb.x = f2tf32(bv.x); tb.y = f2tf32(bv.y);
                tb.z = f2tf32(bv.z); tb.w = f2tf32(bv.w);
                *(uint4*)&Bs[jrow][cc*4] = tb;
            }
        }
        __syncthreads();
        #pragma unroll
        for (int kk = 0; kk < 4; kk++) {
            int kb = kk * 8;
            uint32_t a[2][4];
            #pragma unroll
            for (int mf = 0; mf < 2; mf++) {
                int r = wm0 + mf*16 + gid;
                a[mf][0] = As[r][kb + tig];
                a[mf][1] = As[r+8][kb + tig];
                a[mf][2] = As[r][kb + tig + 4];
                a[mf][3] = As[r+8][kb + tig + 4];
            }
            uint32_t b[8][2];
            #pragma unroll
            for (int nf = 0; nf < 8; nf++) {
                int cn = wn0 + nf*8 + gid;
                b[nf][0] = Bs[kb + tig][cn];
                b[nf][1] = Bs[kb + tig + 4][cn];
            }
            #pragma unroll
            for (int mf = 0; mf < 2; mf++)
                #pragma unroll
                for (int nf = 0; nf < 8; nf++)
                    mma_tf32(acc[mf][nf][0], acc[mf][nf][1], acc[mf][nf][2], acc[mf][nf][3],
                             a[mf][0], a[mf][1], a[mf][2], a[mf][3],
                             b[nf][0], b[nf][1]);
        }
        __syncthreads();
    }
    #pragma unroll
    for (int mf = 0; mf < 2; mf++) {
        #pragma unroll
        for (int half = 0; half < 2; half++) {
            int i = i0 + wm0 + mf*16 + gid + half*8;
            #pragma unroll
            for (int nf = 0; nf < 8; nf++) {
                int cg = c0 + wn0 + nf*8 + tig*2;
                int nn = cg >> 5, dd = cg & 31;
                size_t idx = (size_t)(nn*Ll + i)*Dd + h*DHh + dd;
                float2 gt = *(const float2*)(gate + idx);
                float2 o;
                o.x = acc[mf][nf][half*2 + 0] * gt.x;
                o.y = acc[mf][nf][half*2 + 1] * gt.y;
                *(float2*)(out + idx) = o;
            }
        }
    }
}

// ---------------- host launch ----------------
extern "C" void kernel_launch(void* const* d_in, const int* in_sizes, int n_in,
                              void* d_out, int out_size) {
    const float* msa       = (const float*)d_in[0];
    const float* pair      = (const float*)d_in[1];
    const float* ln_msa_g  = (const float*)d_in[2];
    const float* ln_msa_b  = (const float*)d_in[3];
    const float* ln_pair_g = (const float*)d_in[4];
    const float* ln_pair_b = (const float*)d_in[5];
    const float* Wq_sw     = (const float*)d_in[6];
    const float* bq_sw     = (const float*)d_in[7];
    const float* Wk_sw     = (const float*)d_in[8];
    const float* bk_sw     = (const float*)d_in[9];
    const float* Wq        = (const float*)d_in[10];
    const float* Wk        = (const float*)d_in[11];
    const float* Wv        = (const float*)d_in[12];
    const float* Wb        = (const float*)d_in[13];
    const float* Wg        = (const float*)d_in[14];
    const float* bg        = (const float*)d_in[15];
    const float* Wo        = (const float*)d_in[16];
    const float* bo        = (const float*)d_in[17];
    float* out = (float*)d_out;

    float *q_, *k_, *v_, *gg_, *o_, *qsw_, *sw_, *lg_, *bi_, *mu_, *rs_;
    cudaGetSymbolAddress((void**)&q_,   g_q);
    cudaGetSymbolAddress((void**)&k_,   g_k);
    cudaGetSymbolAddress((void**)&v_,   g_v);
    cudaGetSymbolAddress((void**)&gg_,  g_g);
    cudaGetSymbolAddress((void**)&o_,   g_o);
    cudaGetSymbolAddress((void**)&qsw_, g_qsw);
    cudaGetSymbolAddress((void**)&sw_,  g_sw);
    cudaGetSymbolAddress((void**)&lg_,  g_logits);
    cudaGetSymbolAddress((void**)&bi_,  g_bias);
    cudaGetSymbolAddress((void**)&mu_,  g_mu);
    cudaGetSymbolAddress((void**)&rs_,  g_rs);

    cudaFuncSetAttribute(fusedproj_kernel,
                         cudaFuncAttributeMaxDynamicSharedMemorySize, FP_SMEM_BYTES);

    // 1. per-row LN stats of msa
    rowstat_kernel<<<NL/8, 256>>>(msa, mu_, rs_);
    // 2. q_sw = (LN(msa[n=0]) @ Wq_sw + bq_sw) * scale
    gemm256_tf32<true,false,true><<<dim3(2,3), 256>>>(
        msa, Wq_sw, bq_sw, mu_, rs_, ln_msa_g, ln_msa_b, SCALE, qsw_);
    // 3. fused projections: sw_logits, q, k*scale, v, gate  (msa read once, LN inline)
    fusedproj_kernel<<<NL/128, 512, FP_SMEM_BYTES>>>(
        msa, mu_, rs_, ln_msa_g, ln_msa_b,
        Wk_sw, bk_sw, Wq, Wk, Wv, Wg, bg, qsw_,
        q_, k_, v_, gg_, sw_);
    // 4. softmax over n -> seq_weight
    swsoftmax_kernel<<<Ll*Hh, 256>>>(sw_);
    // 5. pair bias = LN(pair) @ Wb
    pairbias_kernel<<<LLp, 128>>>(pair, ln_pair_g, ln_pair_b, Wb, bi_);
    // 6. logits per head (sw applied on q load, +bias fused)
    logits128_tf32<<<dim3(3,3,8), 256>>>(q_, k_, sw_, bi_, lg_);
    // 7. attn = softmax(logits) over j
    attnsoftmax_kernel<<<Hh*Ll, Ll>>>(lg_);
    // 8. out = (attn @ v) * gate
    outgemm128_tf32<<<dim3((Nn*DHh)/128, 3, 8), 256>>>(lg_, v_, gg_, o_);
    // 9. y = out @ Wo + bo
    gemm256_tf32<false,false,true><<<dim3(2, NL/128), 256>>>(
        o_, Wo, bo, nullptr, nullptr, nullptr, nullptr, 1.f, out);
}

// round 10
// speedup vs baseline: 1.2087x; 1.2087x over previous
#include <cuda_runtime.h>
#include <math.h>
#include <stdint.h>

// Problem constants
#define Nn   256
#define Ll   384
#define Dd   256
#define DP   128
#define Hh   8
#define DHh  32
#define NL   (Nn*Ll)      // 98304 rows
#define LLp  (Ll*Ll)      // 147456
#define EPSF 1e-5f
#define SCALE 0.17677669529663687f  // 1/sqrt(32)

// ---------------- scratch (device globals; no allocation allowed) ----------------
__device__ float g_q   [NL*Dd];   // q projection (raw; seq-weight applied at load)
__device__ float g_k   [NL*Dd];   // k projection (scaled)
__device__ float g_v   [NL*Dd];   // v projection
__device__ float g_g   [NL*Dd];   // gate
__device__ float g_o   [NL*Dd];   // attention output (gated)
__device__ float g_qsw [Ll*Dd];   // seq-weight queries
__device__ float g_sw  [NL*Hh];   // sw logits -> seq weights
__device__ float g_logits[Hh*LLp]; // logits(+bias) -> attn
__device__ float g_bias  [Hh*LLp]; // pair bias
__device__ float g_mu  [NL];
__device__ float g_rs  [NL];

// ---------------- tf32 helpers ----------------
__device__ __forceinline__ uint32_t f2tf32(float f) {
    uint32_t r;
    asm("cvt.rna.tf32.f32 %0, %1;" : "=r"(r) : "f"(f));
    return r;
}

__device__ __forceinline__ void mma_tf32(float& c0, float& c1, float& c2, float& c3,
                                         uint32_t a0, uint32_t a1, uint32_t a2, uint32_t a3,
                                         uint32_t b0, uint32_t b1) {
    asm volatile("mma.sync.aligned.m16n8k8.row.col.f32.tf32.tf32.f32 "
                 "{%0,%1,%2,%3}, {%4,%5,%6,%7}, {%8,%9}, {%0,%1,%2,%3};"
                 : "+f"(c0), "+f"(c1), "+f"(c2), "+f"(c3)
                 : "r"(a0), "r"(a1), "r"(a2), "r"(a3), "r"(b0), "r"(b1));
}

// ---------------- per-row mean/rstd of msa (warp per row) ----------------
__global__ void rowstat_kernel(const float* __restrict__ x,
                               float* __restrict__ mu, float* __restrict__ rs) {
    int row = blockIdx.x * 8 + (threadIdx.x >> 5);
    int lane = threadIdx.x & 31;
    const float4* xp = (const float4*)(x + (size_t)row*Dd);
    float s = 0.f, q = 0.f;
    #pragma unroll
    for (int u = 0; u < 2; u++) {
        float4 v = xp[lane + u*32];
        s += v.x + v.y + v.z + v.w;
        q += v.x*v.x + v.y*v.y + v.z*v.z + v.w*v.w;
    }
    #pragma unroll
    for (int o = 16; o; o >>= 1) {
        s += __shfl_xor_sync(0xffffffffu, s, o);
        q += __shfl_xor_sync(0xffffffffu, q, o);
    }
    if (!lane) {
        float m = s * (1.0f/Dd);
        mu[row] = m;
        rs[row] = rsqrtf(q * (1.0f/Dd) - m*m + EPSF);
    }
}

// ============================================================================
// TF32 GEMM with register-prefetch pipeline.
// C[Mx256] = (optLN(A) @ W + bias)*scale ; optional sigmoid.
// SWL: instead of storing C, compute sw_logits[row][h] = dot(row of (A@W+bias), qsw[row%L])
//      per 32-col head group (heads fully contained in the 128-col block).
// BM=128, BN=128, BK=32, 256 threads (8 warps 4x2), warp tile 32x64.
// ============================================================================
template<bool LN, bool SIG, bool BIAS, bool SWL>
__global__ void __launch_bounds__(256) gemm256_tf32(
        const float* __restrict__ A, const float* __restrict__ W,
        const float* __restrict__ bias,
        const float* __restrict__ mu, const float* __restrict__ rs,
        const float* __restrict__ lng, const float* __restrict__ lnb,
        const float* __restrict__ qsw, float* __restrict__ swl,
        float scale, float* __restrict__ C) {
    __shared__ uint32_t As[128][36];
    __shared__ uint32_t Bs[32][136];
    int tid = threadIdx.x;
    int wid = tid >> 5, lane = tid & 31;
    int gid = lane >> 2, tig = lane & 3;
    int wm0 = (wid >> 1) * 32;
    int wn0 = (wid & 1) * 64;
    int m0 = blockIdx.y * 128, n0 = blockIdx.x * 128;

    // per-thread tile coordinates (kt-independent)
    int arow[4], acol[4], wrow[4], wcol[4];
    float rmu[4], rrs[4];
    #pragma unroll
    for (int u = 0; u < 4; u++) {
        int f = tid + u*256;
        arow[u] = f >> 3;  acol[u] = (f & 7) * 4;
        wrow[u] = f >> 5;  wcol[u] = (f & 31) * 4;
        if (LN) { rmu[u] = mu[m0 + arow[u]]; rrs[u] = rs[m0 + arow[u]]; }
    }

    float4 pa[4], pw[4];
    auto loadT = [&](int kt) {
        #pragma unroll
        for (int u = 0; u < 4; u++)
            pa[u] = *(const float4*)(A + (size_t)(m0+arow[u])*Dd + kt*32 + acol[u]);
        #pragma unroll
        for (int u = 0; u < 4; u++)
            pw[u] = *(const float4*)(W + (size_t)(kt*32+wrow[u])*Dd + n0 + wcol[u]);
    };
    auto storeT = [&](int kt) {
        #pragma unroll
        for (int u = 0; u < 4; u++) {
            float4 v = pa[u];
            if (LN) {
                float4 g4 = *(const float4*)(lng + kt*32 + acol[u]);
                float4 b4 = *(const float4*)(lnb + kt*32 + acol[u]);
                v.x = (v.x - rmu[u])*rrs[u]*g4.x + b4.x;
                v.y = (v.y - rmu[u])*rrs[u]*g4.y + b4.y;
                v.z = (v.z - rmu[u])*rrs[u]*g4.z + b4.z;
                v.w = (v.w - rmu[u])*rrs[u]*g4.w + b4.w;
            }
            uint4 t;
            t.x = f2tf32(v.x); t.y = f2tf32(v.y);
            t.z = f2tf32(v.z); t.w = f2tf32(v.w);
            *(uint4*)&As[arow[u]][acol[u]] = t;
            float4 w4 = pw[u];
            uint4 tw;
            tw.x = f2tf32(w4.x); tw.y = f2tf32(w4.y);
            tw.z = f2tf32(w4.z); tw.w = f2tf32(w4.w);
            *(uint4*)&Bs[wrow[u]][wcol[u]] = tw;
        }
    };

    float acc[2][8][4] = {};
    loadT(0);
    for (int kt = 0; kt < 8; kt++) {
        storeT(kt);
        __syncthreads();
        if (kt < 7) loadT(kt+1);   // LDGs in flight during MMA block
        #pragma unroll
        for (int kk = 0; kk < 4; kk++) {
            int kb = kk * 8;
            uint32_t a[2][4];
            #pragma unroll
            for (int mf = 0; mf < 2; mf++) {
                int r = wm0 + mf*16 + gid;
                a[mf][0] = As[r][kb + tig];
                a[mf][1] = As[r+8][kb + tig];
                a[mf][2] = As[r][kb + tig + 4];
                a[mf][3] = As[r+8][kb + tig + 4];
            }
            uint32_t b[8][2];
            #pragma unroll
            for (int nf = 0; nf < 8; nf++) {
                int cn = wn0 + nf*8 + gid;
                b[nf][0] = Bs[kb + tig][cn];
                b[nf][1] = Bs[kb + tig + 4][cn];
            }
            #pragma unroll
            for (int mf = 0; mf < 2; mf++)
                #pragma unroll
                for (int nf = 0; nf < 8; nf++)
                    mma_tf32(acc[mf][nf][0], acc[mf][nf][1], acc[mf][nf][2], acc[mf][nf][3],
                             a[mf][0], a[mf][1], a[mf][2], a[mf][3],
                             b[nf][0], b[nf][1]);
        }
        __syncthreads();
    }

    if (SWL) {
        // sw_logits epilogue: dot each head's 32 output cols with qsw[row%L]
        #pragma unroll
        for (int mf = 0; mf < 2; mf++) {
            #pragma unroll
            for (int half = 0; half < 2; half++) {
                int row = m0 + wm0 + mf*16 + gid + half*8;
                int i = row % Ll;
                float p0 = 0.f, p1 = 0.f;
                #pragma unroll
                for (int nf = 0; nf < 8; nf++) {
                    int col = n0 + wn0 + nf*8 + tig*2;
                    float v0 = acc[mf][nf][half*2 + 0] + bias[col];
                    float v1 = acc[mf][nf][half*2 + 1] + bias[col+1];
                    float2 qv = *(const float2*)(qsw + (size_t)i*Dd + col);
                    float contrib = v0*qv.x + v1*qv.y;
                    if (nf < 4) p0 += contrib; else p1 += contrib;
                }
                p0 += __shfl_xor_sync(0xffffffffu, p0, 1);
                p0 += __shfl_xor_sync(0xffffffffu, p0, 2);
                p1 += __shfl_xor_sync(0xffffffffu, p1, 1);
                p1 += __shfl_xor_sync(0xffffffffu, p1, 2);
                if (tig == 0) {
                    int h0 = (n0 + wn0) >> 5;
                    swl[(size_t)row*Hh + h0]     = p0;
                    swl[(size_t)row*Hh + h0 + 1] = p1;
                }
            }
        }
    } else {
        #pragma unroll
        for (int mf = 0; mf < 2; mf++) {
            #pragma unroll
            for (int half = 0; half < 2; half++) {
                int row = m0 + wm0 + mf*16 + gid + half*8;
                #pragma unroll
                for (int nf = 0; nf < 8; nf++) {
                    int col = n0 + wn0 + nf*8 + tig*2;
                    float v0 = acc[mf][nf][half*2 + 0];
                    float v1 = acc[mf][nf][half*2 + 1];
                    if (BIAS) { v0 += bias[col]; v1 += bias[col+1]; }
                    v0 *= scale; v1 *= scale;
                    if (SIG) {
                        v0 = 1.f / (1.f + expf(-v0));
                        v1 = 1.f / (1.f + expf(-v1));
                    }
                    float2 o; o.x = v0; o.y = v1;
                    *(float2*)(C + (size_t)row*Dd + col) = o;
                }
            }
        }
    }
}

// ---------------- softmax over n (256) for each (i,h) ----------------
__global__ void swsoftmax_kernel(float* __restrict__ sw) {
    __shared__ float sm[8];
    __shared__ float red;
    int ih = blockIdx.x;             // i*H + h
    int n = threadIdx.x;             // 256
    int lane = n & 31, w = n >> 5;
    float v = sw[(size_t)n*(Ll*Hh) + ih];
    float mx = v;
    #pragma unroll
    for (int o = 16; o; o >>= 1) mx = fmaxf(mx, __shfl_down_sync(0xffffffffu, mx, o));
    if (!lane) sm[w] = mx;
    __syncthreads();
    if (w == 0) {
        float x = (lane < 8) ? sm[lane] : -3.4e38f;
        #pragma unroll
        for (int o = 16; o; o >>= 1) x = fmaxf(x, __shfl_down_sync(0xffffffffu, x, o));
        if (!lane) red = x;
    }
    __syncthreads();
    mx = red;
    float e = expf(v - mx);
    float s = e;
    #pragma unroll
    for (int o = 16; o; o >>= 1) s += __shfl_down_sync(0xffffffffu, s, o);
    __syncthreads();
    if (!lane) sm[w] = s;
    __syncthreads();
    if (w == 0) {
        float x = (lane < 8) ? sm[lane] : 0.f;
        #pragma unroll
        for (int o = 16; o; o >>= 1) x += __shfl_down_sync(0xffffffffu, x, o);
        if (!lane) red = x;
    }
    __syncthreads();
    sw[(size_t)n*(Ll*Hh) + ih] = e / red;
}

// ---------------- pair bias: LN(pair row) @ Wb -> bias[h][i][j] ----------------
__global__ void pairbias_kernel(const float* __restrict__ pair, const float* __restrict__ g,
                                const float* __restrict__ b, const float* __restrict__ Wb,
                                float* __restrict__ bias) {
    __shared__ float s1[4], s2[4];
    __shared__ float hp[4][8];
    int ij = blockIdx.x;             // i*L + j
    int t = threadIdx.x;             // 128
    int lane = t & 31, w = t >> 5;
    float v = pair[(size_t)ij*DP + t];
    float s = v, q = v*v;
    #pragma unroll
    for (int o = 16; o; o >>= 1) {
        s += __shfl_down_sync(0xffffffffu, s, o);
        q += __shfl_down_sync(0xffffffffu, q, o);
    }
    if (!lane) { s1[w] = s; s2[w] = q; }
    __syncthreads();
    if (w == 0) {
        float ss = (lane < 4) ? s1[lane] : 0.f;
        float qq = (lane < 4) ? s2[lane] : 0.f;
        #pragma unroll
        for (int o = 16; o; o >>= 1) {
            ss += __shfl_down_sync(0xffffffffu, ss, o);
            qq += __shfl_down_sync(0xffffffffu, qq, o);
        }
        if (!lane) { s1[0] = ss; s2[0] = qq; }
    }
    __syncthreads();
    float mu = s1[0] * (1.0f/DP);
    float var = s2[0] * (1.0f/DP) - mu*mu;
    float ln = (v - mu) * rsqrtf(var + EPSF) * g[t] + b[t];
    float p[8];
    #pragma unroll
    for (int h = 0; h < 8; h++) p[h] = ln * Wb[t*Hh + h];
    #pragma unroll
    for (int h = 0; h < 8; h++)
        #pragma unroll
        for (int o = 16; o; o >>= 1) p[h] += __shfl_down_sync(0xffffffffu, p[h], o);
    if (!lane) {
        #pragma unroll
        for (int h = 0; h < 8; h++) hp[w][h] = p[h];
    }
    __syncthreads();
    if (t < 8) {
        float x = hp[0][t] + hp[1][t] + hp[2][t] + hp[3][t];
        bias[(size_t)t*LLp + ij] = x;
    }
}

// ============================================================================
// TF32 logits 128x128 with register-prefetch:
// logits[h][i][j] = sum_{n,d} (q*sw)[n,i,h,d]*k[n,j,h,d] + bias
// grid (3, 3, 8), 256 threads (8 warps 4x2).
// ============================================================================
__global__ void __launch_bounds__(256) logits128_tf32(const float* __restrict__ q,
        const float* __restrict__ kmat, const float* __restrict__ sw,
        const float* __restrict__ bias, float* __restrict__ out) {
    __shared__ uint32_t As[128][36];   // q tile [i][d]
    __shared__ uint32_t Bs[128][36];   // k tile [j][d]
    int h = blockIdx.z;
    int i0 = blockIdx.y * 128, j0 = blockIdx.x * 128;
    int tid = threadIdx.x;
    int wid = tid >> 5, lane = tid & 31;
    int gid = lane >> 2, tig = lane & 3;
    int wm0 = (wid >> 1) * 32;
    int wn0 = (wid & 1) * 64;

    int lrow[4], lcol[4];
    #pragma unroll
    for (int u = 0; u < 4; u++) {
        int f = tid + u*256;
        lrow[u] = f >> 3; lcol[u] = (f & 7) * 4;
    }
    float4 pq[4], pk[4]; float psw[4];
    auto loadT = [&](int n) {
        #pragma unroll
        for (int u = 0; u < 4; u++) {
            int gi = n*Ll + i0 + lrow[u];
            psw[u] = sw[(size_t)gi*Hh + h];
            pq[u] = *(const float4*)(q + (size_t)gi*Dd + h*DHh + lcol[u]);
            int gj = n*Ll + j0 + lrow[u];
            pk[u] = *(const float4*)(kmat + (size_t)gj*Dd + h*DHh + lcol[u]);
        }
    };
    auto storeT = [&]() {
        #pragma unroll
        for (int u = 0; u < 4; u++) {
            uint4 ta;
            ta.x = f2tf32(pq[u].x*psw[u]); ta.y = f2tf32(pq[u].y*psw[u]);
            ta.z = f2tf32(pq[u].z*psw[u]); ta.w = f2tf32(pq[u].w*psw[u]);
            *(uint4*)&As[lrow[u]][lcol[u]] = ta;
            uint4 tb;
            tb.x = f2tf32(pk[u].x); tb.y = f2tf32(pk[u].y);
            tb.z = f2tf32(pk[u].z); tb.w = f2tf32(pk[u].w);
            *(uint4*)&Bs[lrow[u]][lcol[u]] = tb;
        }
    };

    float acc[2][8][4] = {};
    loadT(0);
    for (int n = 0; n < Nn; n++) {
        storeT();
        __syncthreads();
        if (n < Nn-1) loadT(n+1);
        #pragma unroll
        for (int kk = 0; kk < 4; kk++) {
            int kb = kk * 8;
            uint32_t a[2][4];
            #pragma unroll
            for (int mf = 0; mf < 2; mf++) {
                int r = wm0 + mf*16 + gid;
                a[mf][0] = As[r][kb + tig];
                a[mf][1] = As[r+8][kb + tig];
                a[mf][2] = As[r][kb + tig + 4];
                a[mf][3] = As[r+8][kb + tig + 4];
            }
            uint32_t b[8][2];
            #pragma unroll
            for (int nf = 0; nf < 8; nf++) {
                int cn = wn0 + nf*8 + gid;
                b[nf][0] = Bs[cn][kb + tig];
                b[nf][1] = Bs[cn][kb + tig + 4];
            }
            #pragma unroll
            for (int mf = 0; mf < 2; mf++)
                #pragma unroll
                for (int nf = 0; nf < 8; nf++)
                    mma_tf32(acc[mf][nf][0], acc[mf][nf][1], acc[mf][nf][2], acc[mf][nf][3],
                             a[mf][0], a[mf][1], a[mf][2], a[mf][3],
                             b[nf][0], b[nf][1]);
        }
        __syncthreads();
    }
    #pragma unroll
    for (int mf = 0; mf < 2; mf++) {
        #pragma unroll
        for (int half = 0; half < 2; half++) {
            int i = i0 + wm0 + mf*16 + gid + half*8;
            #pragma unroll
            for (int nf = 0; nf < 8; nf++) {
                int j = j0 + wn0 + nf*8 + tig*2;
                size_t idx = (size_t)h*LLp + (size_t)i*Ll + j;
                float2 bb = *(const float2*)(bias + idx);
                float2 o;
                o.x = acc[mf][nf][half*2 + 0] + bb.x;
                o.y = acc[mf][nf][half*2 + 1] + bb.y;
                *(float2*)(out + idx) = o;
            }
        }
    }
}

// ---------------- softmax over j (384) for each (h, i) ----------------
__global__ void attnsoftmax_kernel(float* __restrict__ logits) {
    __shared__ float sm[12];
    __shared__ float red;
    int hi = blockIdx.x;             // h*L + i
    size_t base = (size_t)hi * Ll;
    int j = threadIdx.x;             // 384 threads, 12 warps
    int lane = j & 31, w = j >> 5;
    float v = logits[base + j];
    float mx = v;
    #pragma unroll
    for (int o = 16; o; o >>= 1) mx = fmaxf(mx, __shfl_down_sync(0xffffffffu, mx, o));
    if (!lane) sm[w] = mx;
    __syncthreads();
    if (w == 0) {
        float x = (lane < 12) ? sm[lane] : -3.4e38f;
        #pragma unroll
        for (int o = 16; o; o >>= 1) x = fmaxf(x, __shfl_down_sync(0xffffffffu, x, o));
        if (!lane) red = x;
    }
    __syncthreads();
    mx = red;
    float e = expf(v - mx);
    float s = e;
    #pragma unroll
    for (int o = 16; o; o >>= 1) s += __shfl_down_sync(0xffffffffu, s, o);
    __syncthreads();
    if (!lane) sm[w] = s;
    __syncthreads();
    if (w == 0) {
        float x = (lane < 12) ? sm[lane] : 0.f;
        #pragma unroll
        for (int o = 16; o; o >>= 1) x += __shfl_down_sync(0xffffffffu, x, o);
        if (!lane) red = x;
    }
    __syncthreads();
    logits[base + j] = e / red;
}

// ============================================================================
// TF32 attn@V 128x128 with register-prefetch + fused gate: out = (attn @ v) * gate
// grid (64, 3, 8), 256 threads (8 warps 4x2). c = n_local*32 + d.
// ============================================================================
__global__ void __launch_bounds__(256) outgemm128_tf32(const float* __restrict__ attn,
        const float* __restrict__ v, const float* __restrict__ gate,
        float* __restrict__ out) {
    __shared__ uint32_t As[128][36];   // attn [i][j]
    __shared__ uint32_t Bs[32][136];   // v [j][c]
    int h = blockIdx.z;
    int i0 = blockIdx.y * 128, c0 = blockIdx.x * 128;
    int tid = threadIdx.x;
    int wid = tid >> 5, lane = tid & 31;
    int gid = lane >> 2, tig = lane & 3;
    int wm0 = (wid >> 1) * 32;
    int wn0 = (wid & 1) * 64;

    int xrow[4], xcol[4], vrow[4], vcol[4], vnn[4], vdd[4];
    #pragma unroll
    for (int u = 0; u < 4; u++) {
        int f = tid + u*256;
        xrow[u] = f >> 3; xcol[u] = (f & 7) * 4;
        vrow[u] = f >> 5;
        int cc = f & 31;
        vcol[u] = cc * 4;
        int cg = c0 + cc*4;
        vnn[u] = cg >> 5; vdd[u] = cg & 31;
    }
    float4 pa[4], pv[4];
    auto loadT = [&](int jt) {
        int j0 = jt * 32;
        #pragma unroll
        for (int u = 0; u < 4; u++) {
            pa[u] = *(const float4*)(attn + (size_t)h*LLp + (size_t)(i0 + xrow[u])*Ll + j0 + xcol[u]);
            pv[u] = *(const float4*)(v + (size_t)(vnn[u]*Ll + j0 + vrow[u])*Dd + h*DHh + vdd[u]);
        }
    };
    auto storeT = [&]() {
        #pragma unroll
        for (int u = 0; u < 4; u++) {
            uint4 ta;
            ta.x = f2tf32(pa[u].x); ta.y = f2tf32(pa[u].y);
            ta.z = f2tf32(pa[u].z); ta.w = f2tf32(pa[u].w);
            *(uint4*)&As[xrow[u]][xcol[u]] = ta;
            uint4 tb;
            tb.x = f2tf32(pv[u].x); tb.y = f2tf32(pv[u].y);
            tb.z = f2tf32(pv[u].z); tb.w = f2tf32(pv[u].w);
            *(uint4*)&Bs[vrow[u]][vcol[u]] = tb;
        }
    };

    float acc[2][8][4] = {};
    loadT(0);
    for (int jt = 0; jt < 12; jt++) {
        storeT();
        __syncthreads();
        if (jt < 11) loadT(jt+1);
        #pragma unroll
        for (int kk = 0; kk < 4; kk++) {
            int kb = kk * 8;
            uint32_t a[2][4];
            #pragma unroll
            for (int mf = 0; mf < 2; mf++) {
                int r = wm0 + mf*16 + gid;
                a[mf][0] = As[r][kb + tig];
                a[mf][1] = As[r+8][kb + tig];
                a[mf][2] = As[r][kb + tig + 4];
                a[mf][3] = As[r+8][kb + tig + 4];
            }
            uint32_t b[8][2];
            #pragma unroll
            for (int nf = 0; nf < 8; nf++) {
                int cn = wn0 + nf*8 + gid;
                b[nf][0] = Bs[kb + tig][cn];
                b[nf][1] = Bs[kb + tig + 4][cn];
            }
            #pragma unroll
            for (int mf = 0; mf < 2; mf++)
                #pragma unroll
                for (int nf = 0; nf < 8; nf++)
                    mma_tf32(acc[mf][nf][0], acc[mf][nf][1], acc[mf][nf][2], acc[mf][nf][3],
                             a[mf][0], a[mf][1], a[mf][2], a[mf][3],
                             b[nf][0], b[nf][1]);
        }
        __syncthreads();
    }
    #pragma unroll
    for (int mf = 0; mf < 2; mf++) {
        #pragma unroll
        for (int half = 0; half < 2; half++) {
            int i = i0 + wm0 + mf*16 + gid + half*8;
            #pragma unroll
            for (int nf = 0; nf < 8; nf++) {
                int cg = c0 + wn0 + nf*8 + tig*2;
                int nn = cg >> 5, dd = cg & 31;
                size_t idx = (size_t)(nn*Ll + i)*Dd + h*DHh + dd;
                float2 gt = *(const float2*)(gate + idx);
                float2 o;
                o.x = acc[mf][nf][half*2 + 0] * gt.x;
                o.y = acc[mf][nf][half*2 + 1] * gt.y;
                *(float2*)(out + idx) = o;
            }
        }
    }
}

// ---------------- host launch ----------------
extern "C" void kernel_launch(void* const* d_in, const int* in_sizes, int n_in,
                              void* d_out, int out_size) {
    const float* msa       = (const float*)d_in[0];
    const float* pair      = (const float*)d_in[1];
    const float* ln_msa_g  = (const float*)d_in[2];
    const float* ln_msa_b  = (const float*)d_in[3];
    const float* ln_pair_g = (const float*)d_in[4];
    const float* ln_pair_b = (const float*)d_in[5];
    const float* Wq_sw     = (const float*)d_in[6];
    const float* bq_sw     = (const float*)d_in[7];
    const float* Wk_sw     = (const float*)d_in[8];
    const float* bk_sw     = (const float*)d_in[9];
    const float* Wq        = (const float*)d_in[10];
    const float* Wk        = (const float*)d_in[11];
    const float* Wv        = (const float*)d_in[12];
    const float* Wb        = (const float*)d_in[13];
    const float* Wg        = (const float*)d_in[14];
    const float* bg        = (const float*)d_in[15];
    const float* Wo        = (const float*)d_in[16];
    const float* bo        = (const float*)d_in[17];
    float* out = (float*)d_out;

    float *q_, *k_, *v_, *gg_, *o_, *qsw_, *sw_, *lg_, *bi_, *mu_, *rs_;
    cudaGetSymbolAddress((void**)&q_,   g_q);
    cudaGetSymbolAddress((void**)&k_,   g_k);
    cudaGetSymbolAddress((void**)&v_,   g_v);
    cudaGetSymbolAddress((void**)&gg_,  g_g);
    cudaGetSymbolAddress((void**)&o_,   g_o);
    cudaGetSymbolAddress((void**)&qsw_, g_qsw);
    cudaGetSymbolAddress((void**)&sw_,  g_sw);
    cudaGetSymbolAddress((void**)&lg_,  g_logits);
    cudaGetSymbolAddress((void**)&bi_,  g_bias);
    cudaGetSymbolAddress((void**)&mu_,  g_mu);
    cudaGetSymbolAddress((void**)&rs_,  g_rs);

    dim3 gproj(2, NL/128);   // (256/128, 98304/128)

    // 1. per-row LN stats of msa
    rowstat_kernel<<<NL/8, 256>>>(msa, mu_, rs_);
    // 2. q_sw = (LN(msa[n=0]) @ Wq_sw + bq_sw) * scale   (rows 0..383)
    gemm256_tf32<true,false,true,false><<<dim3(2,3), 256>>>(
        msa, Wq_sw, bq_sw, mu_, rs_, ln_msa_g, ln_msa_b,
        nullptr, nullptr, SCALE, qsw_);
    // 3. sw_logits = (LN(msa) @ Wk_sw + bk_sw) . qsw   (ksw never stored)
    gemm256_tf32<true,false,true,true><<<gproj, 256>>>(
        msa, Wk_sw, bk_sw, mu_, rs_, ln_msa_g, ln_msa_b,
        qsw_, sw_, 1.f, nullptr);
    // 4. q = LN(msa) @ Wq
    gemm256_tf32<true,false,false,false><<<gproj, 256>>>(
        msa, Wq, nullptr, mu_, rs_, ln_msa_g, ln_msa_b,
        nullptr, nullptr, 1.f, q_);
    // 5. k = (LN(msa) @ Wk) * scale
    gemm256_tf32<true,false,false,false><<<gproj, 256>>>(
        msa, Wk, nullptr, mu_, rs_, ln_msa_g, ln_msa_b,
        nullptr, nullptr, SCALE, k_);
    // 6. v = LN(msa) @ Wv
    gemm256_tf32<true,false,false,false><<<gproj, 256>>>(
        msa, Wv, nullptr, mu_, rs_, ln_msa_g, ln_msa_b,
        nullptr, nullptr, 1.f, v_);
    // 7. gate = sigmoid(LN(msa) @ Wg + bg)
    gemm256_tf32<true,true,true,false><<<gproj, 256>>>(
        msa, Wg, bg, mu_, rs_, ln_msa_g, ln_msa_b,
        nullptr, nullptr, 1.f, gg_);
    // 8. softmax over n -> seq_weight
    swsoftmax_kernel<<<Ll*Hh, 256>>>(sw_);
    // 9. pair bias = LN(pair) @ Wb
    pairbias_kernel<<<LLp, 128>>>(pair, ln_pair_g, ln_pair_b, Wb, bi_);
    // 10. logits per head (sw applied on q load, +bias fused)
    logits128_tf32<<<dim3(3,3,8), 256>>>(q_, k_, sw_, bi_, lg_);
    // 11. attn = softmax(logits) over j
    attnsoftmax_kernel<<<Hh*Ll, Ll>>>(lg_);
    // 12. out = (attn @ v) * gate
    outgemm128_tf32<<<dim3((Nn*DHh)/128, 3, 8), 256>>>(lg_, v_, gg_, o_);
    // 13. y = out @ Wo + bo
    gemm256_tf32<false,false,true,false><<<dim3(2, NL/128), 256>>>(
        o_, Wo, bo, nullptr, nullptr, nullptr, nullptr,
        nullptr, nullptr, 1.f, out);
}